// round 13
// baseline (speedup 1.0000x reference)
#include <cuda_runtime.h>
#include <cuda_fp16.h>
#include <math.h>
#include <stdint.h>

#define S_TOK 3120
#define DIM   1536
#define NH    12
#define HD    128
#define FRAME 520
#define TK    64
#define GK    1536
#define VT_PAD 3136   /* 49*64 */

/* ---- scratch (static device globals) ---- */
__device__ float  g_q[S_TOK * DIM];
__device__ float  g_k[S_TOK * DIM];
__device__ float  g_v[S_TOK * DIM];
__device__ __half g_oh[S_TOK * DIM];
__device__ __half g_xh[S_TOK * DIM];
__device__ __half g_wTh[4][GK * GK];
__device__ __half g_qhh[S_TOK * DIM];
__device__ __half g_qll[S_TOK * DIM];
__device__ __half g_khh[S_TOK * DIM];
__device__ __half g_kll[S_TOK * DIM];
__device__ __half g_vt[NH * HD * VT_PAD];

__device__ __forceinline__ void mma_f16(float* c, const uint32_t* a, uint32_t b0, uint32_t b1) {
    asm volatile(
        "mma.sync.aligned.m16n8k16.row.col.f32.f16.f16.f32 "
        "{%0,%1,%2,%3}, {%4,%5,%6,%7}, {%8,%9}, {%0,%1,%2,%3};"
        : "+f"(c[0]), "+f"(c[1]), "+f"(c[2]), "+f"(c[3])
        : "r"(a[0]), "r"(a[1]), "r"(a[2]), "r"(a[3]), "r"(b0), "r"(b1));
}

__device__ __forceinline__ void cp_async16(void* smem_dst, const void* gsrc, bool valid) {
    uint32_t saddr = (uint32_t)__cvta_generic_to_shared(smem_dst);
    int sz = valid ? 16 : 0;
    asm volatile("cp.async.cg.shared.global [%0], [%1], 16, %2;\n"
                 :: "r"(saddr), "l"(gsrc), "r"(sz));
}
__device__ __forceinline__ void cp_commit() { asm volatile("cp.async.commit_group;\n"); }
template <int N>
__device__ __forceinline__ void cp_wait() { asm volatile("cp.async.wait_group %0;\n" :: "n"(N)); }

/* fast 2^y on the FMA pipe (y <= 0; masked values clamp to 2^-60 ~= 0).
   Max rel err ~4e-5 — below the fp16 rounding applied to P afterwards. */
__device__ __forceinline__ float fexp2f(float y) {
    y = fmaxf(y, -60.f);
    float t = y + 12582912.f;                       /* 1.5 * 2^23 round-to-int */
    int   j = __float_as_int(t) - 0x4B400000;
    float f = y - (t - 12582912.f);                 /* f in [-0.5, 0.5] */
    float p = 1.0f + f * (0.69314718f + f * (0.24022651f +
                    f * (0.05550411f + f * 0.00961813f)));
    return __int_as_float(__float_as_int(p) + (j << 23));
}

/* ============== pre-pass kernels ============== */
__global__ __launch_bounds__(256) void transpose_half_kernel(
    const float* __restrict__ w0, const float* __restrict__ w1,
    const float* __restrict__ w2, const float* __restrict__ w3,
    __half* __restrict__ dstbase)
{
    __shared__ float tile[32][33];
    const float* src = (blockIdx.z == 0) ? w0 : (blockIdx.z == 1) ? w1 : (blockIdx.z == 2) ? w2 : w3;
    __half* dst = dstbase + (size_t)blockIdx.z * GK * GK;
    const int tx = threadIdx.x & 31, ty = threadIdx.x >> 5;
    int x = blockIdx.x * 32 + tx;
    int y = blockIdx.y * 32 + ty;
#pragma unroll
    for (int i = 0; i < 32; i += 8)
        tile[ty + i][tx] = src[(size_t)(y + i) * GK + x];
    __syncthreads();
    x = blockIdx.y * 32 + tx;
    y = blockIdx.x * 32 + ty;
#pragma unroll
    for (int i = 0; i < 32; i += 8)
        dst[(size_t)(y + i) * GK + x] = __float2half_rn(tile[tx][ty + i]);
}

__global__ __launch_bounds__(256) void convert_x_kernel(const float* __restrict__ x)
{
    int i = (blockIdx.x * 256 + threadIdx.x) * 4;
    if (i < S_TOK * DIM) {
        float4 v = *(const float4*)&x[i];
        *(__half2*)&g_xh[i]     = __floats2half2_rn(v.x, v.y);
        *(__half2*)&g_xh[i + 2] = __floats2half2_rn(v.z, v.w);
    }
}

__global__ __launch_bounds__(256) void v_trans_kernel()
{
    __shared__ float tile[32][33];
    const int tx = threadIdx.x & 31, ty = threadIdx.x >> 5;
    const int t0 = blockIdx.x * 32;
    const int d0 = blockIdx.y * 32;
#pragma unroll
    for (int i = 0; i < 32; i += 8) {
        const int tok = t0 + ty + i;
        tile[ty + i][tx] = (tok < S_TOK) ? g_v[(size_t)tok * DIM + d0 + tx] : 0.f;
    }
    __syncthreads();
#pragma unroll
    for (int i = 0; i < 32; i += 8) {
        const int d = d0 + ty + i;
        g_vt[(size_t)d * VT_PAD + t0 + tx] = __float2half_rn(tile[tx][ty + i]);
    }
}

/* ============== fp16 GEMM core (128 thr, 64x64 warp tiles) ============== */
#define BM 128
#define BN 128
#define BKH 32
#define GST 40

__device__ __forceinline__ void gemm_body(
    const __half* __restrict__ A, const __half* __restrict__ Bt,
    const float* __restrict__ bias, float* __restrict__ C,
    int bm, int bn, int M)
{
    __shared__ __half As[2][BM][GST];
    __shared__ __half Bs[2][BN][GST];

    const int tid  = threadIdx.x;
    const int warp = tid >> 5;
    const int lane = tid & 31;
    const int gr   = lane >> 2;
    const int gc   = lane & 3;

    const int wm = (warp & 1) * 64;
    const int wn = (warp >> 1) * 64;

    float acc[4][8][4];
#pragma unroll
    for (int mi = 0; mi < 4; mi++)
#pragma unroll
        for (int nj = 0; nj < 8; nj++)
#pragma unroll
            for (int e = 0; e < 4; e++) acc[mi][nj][e] = 0.f;

    int crow[4]; int cc16[4];
#pragma unroll
    for (int i = 0; i < 4; i++) {
        const int cid = i * 128 + tid;
        crow[i] = cid >> 2;
        cc16[i] = cid & 3;
    }

    const int NT = GK / BKH;

#pragma unroll
    for (int i = 0; i < 4; i++) {
        cp_async16(&As[0][crow[i]][cc16[i] * 8], &A[(size_t)(bm + crow[i]) * GK + cc16[i] * 8], (bm + crow[i]) < M);
        cp_async16(&Bs[0][crow[i]][cc16[i] * 8], &Bt[(size_t)(bn + crow[i]) * GK + cc16[i] * 8], true);
    }
    cp_commit();

    for (int t = 0; t < NT; t++) {
        if (t + 1 < NT) {
            const int kt = (t + 1) * BKH;
            const int s1 = (t + 1) & 1;
#pragma unroll
            for (int i = 0; i < 4; i++) {
                cp_async16(&As[s1][crow[i]][cc16[i] * 8], &A[(size_t)(bm + crow[i]) * GK + kt + cc16[i] * 8], (bm + crow[i]) < M);
                cp_async16(&Bs[s1][crow[i]][cc16[i] * 8], &Bt[(size_t)(bn + crow[i]) * GK + kt + cc16[i] * 8], true);
            }
        }
        cp_commit();
        cp_wait<1>();
        __syncthreads();

        const int b = t & 1;
#pragma unroll
        for (int ks = 0; ks < 2; ks++) {
            const int kh = ks * 16 + 2 * gc;
            uint32_t af[4][4];
#pragma unroll
            for (int mi = 0; mi < 4; mi++) {
                const int m0 = wm + mi * 16 + gr;
                af[mi][0] = *(const uint32_t*)&As[b][m0][kh];
                af[mi][1] = *(const uint32_t*)&As[b][m0 + 8][kh];
                af[mi][2] = *(const uint32_t*)&As[b][m0][kh + 8];
                af[mi][3] = *(const uint32_t*)&As[b][m0 + 8][kh + 8];
            }
#pragma unroll
            for (int nj = 0; nj < 8; nj++) {
                const int n0 = wn + nj * 8 + gr;
                uint32_t b0 = *(const uint32_t*)&Bs[b][n0][kh];
                uint32_t b1 = *(const uint32_t*)&Bs[b][n0][kh + 8];
#pragma unroll
                for (int mi = 0; mi < 4; mi++)
                    mma_f16(acc[mi][nj], af[mi], b0, b1);
            }
        }
        __syncthreads();
    }

#pragma unroll
    for (int mi = 0; mi < 4; mi++) {
        const int row0 = bm + wm + mi * 16 + gr;
        const int row1 = row0 + 8;
#pragma unroll
        for (int nj = 0; nj < 8; nj++) {
            const int col = bn + wn + nj * 8 + 2 * gc;
            const float b0 = bias[col];
            const float b1 = bias[col + 1];
            if (row0 < M)
                *(float2*)&C[(size_t)row0 * GK + col] = make_float2(acc[mi][nj][0] + b0, acc[mi][nj][1] + b1);
            if (row1 < M)
                *(float2*)&C[(size_t)row1 * GK + col] = make_float2(acc[mi][nj][2] + b0, acc[mi][nj][3] + b1);
        }
    }
}

__global__ __launch_bounds__(128, 2) void gemm_qkv_kernel(
    const float* __restrict__ bq, const float* __restrict__ bk, const float* __restrict__ bv)
{
    const int bng = blockIdx.x * BN;
    const int which = bng / GK;
    const int bn = bng - which * GK;
    const __half* Bt = &g_wTh[which][0];
    const float* bias = (which == 0) ? bq : (which == 1) ? bk : bv;
    float* C = (which == 0) ? g_q : (which == 1) ? g_k : g_v;
    gemm_body(g_xh, Bt, bias, C, blockIdx.y * BM, bn, S_TOK);
}

__global__ __launch_bounds__(128, 2) void gemm_out_kernel(
    const float* __restrict__ bias, float* __restrict__ C)
{
    gemm_body(g_oh, &g_wTh[3][0], bias, C, blockIdx.y * BM, blockIdx.x * BN, S_TOK);
}

/* ============ fused RMSNorm + RoPE -> half hi/lo ============ */
__global__ __launch_bounds__(256) void rms_rope_kernel(
    const float* __restrict__ fcos, const float* __restrict__ fsin,
    const float* __restrict__ gq, const float* __restrict__ gk)
{
    const int row   = blockIdx.x;
    const int which = blockIdx.y;
    const float* buf = which ? g_k : g_q;
    __half* dh       = which ? g_khh : g_qhh;
    __half* dl       = which ? g_kll : g_qll;
    const float* g   = which ? gk : gq;
    const int tid    = threadIdx.x;

    const float* p = buf + (size_t)row * DIM;
    float ss = 0.f;
    for (int i = tid; i < DIM; i += 256) { float v = p[i]; ss += v * v; }

    __shared__ float red[256];
    red[tid] = ss;
    __syncthreads();
    for (int s = 128; s > 0; s >>= 1) {
        if (tid < s) red[tid] += red[tid + s];
        __syncthreads();
    }
    const float inv = rsqrtf(red[0] * (1.0f / DIM) + 1e-6f);

    const int f  = row / FRAME;
    const int hh = (row / 26) % 20;
    const int ww = row % 26;

    for (int pi = tid; pi < NH * 64; pi += 256) {
        const int head = pi >> 6;
        const int c    = pi & 63;
        const int pr   = (c < 22) ? f : ((c < 43) ? hh : ww);
        const float cs = fcos[pr * 64 + c];
        const float sn = fsin[pr * 64 + c];
        const size_t base = (size_t)row * DIM + head * HD + 2 * c;
        const float xr = buf[base]     * inv * g[head * HD + 2 * c];
        const float xi = buf[base + 1] * inv * g[head * HD + 2 * c + 1];
        const float r0 = xr * cs - xi * sn;
        const float r1 = xr * sn + xi * cs;
        const __half h0 = __float2half_rn(r0);
        const __half h1 = __float2half_rn(r1);
        *(__half2*)&dh[base] = __halves2half2(h0, h1);
        *(__half2*)&dl[base] = __floats2half2_rn(r0 - __half2float(h0), r1 - __half2float(h1));
    }
}

/* ========== fp16 flash attention: 128q x 64k, FMA-pipe softmax ========== */
#define TQ2 128
#define QS 136
#define VS 72
#define PS 72
#define O_QH 0
#define O_QL (TQ2 * QS)
#define O_K  (2 * TQ2 * QS)
#define K_STG (2 * 64 * QS)
#define O_V  (O_K + 2 * K_STG)
#define V_STG (HD * VS)
#define O_P  (O_V + 2 * V_STG)
#define ATTN_HALVES (O_P + TQ2 * PS)
#define ATTN_SMEM_BYTES (ATTN_HALVES * 2)

__global__ __launch_bounds__(256) void attn_f16_kernel()
{
    extern __shared__ __half sh[];
    const int tid  = threadIdx.x;
    const int warp = tid >> 5;
    const int lane = tid & 31;
    const int gr   = lane >> 2;
    const int gc   = lane & 3;
    const int qs   = blockIdx.x * TQ2;
    const int h    = blockIdx.y;

#pragma unroll
    for (int i = 0; i < 8; i++) {
        const int id = i * 256 + tid;
        const int r = id >> 4, ch = id & 15;
        const bool v = (qs + r) < S_TOK;
        const size_t gsrc = (size_t)(qs + r) * DIM + h * HD + ch * 8;
        cp_async16(sh + O_QH + r * QS + ch * 8, &g_qhh[gsrc], v);
        cp_async16(sh + O_QL + r * QS + ch * 8, &g_qll[gsrc], v);
    }

    const int fi_min = qs / FRAME;
    const int fi_max = min(qs + TQ2 - 1, S_TOK - 1) / FRAME;
    int lo = fi_min - 3; if (lo < 0) lo = 0;
    lo *= FRAME;
    int hi = (fi_max + 1) * FRAME; if (hi > S_TOK) hi = S_TOK;
    int tiles[52]; int ntile = 0;
    if (lo <= FRAME) {
        for (int ks = 0; ks < hi; ks += TK) tiles[ntile++] = ks;
    } else {
        for (int ks = 0; ks < FRAME; ks += TK) tiles[ntile++] = ks;
        for (int ks = (lo / TK) * TK; ks < hi; ks += TK) tiles[ntile++] = ks;
    }

    auto load_kv = [&](int ks, int s) {
        __half* Khp = sh + O_K + s * K_STG;
        __half* Klp = Khp + 64 * QS;
        __half* Vp  = sh + O_V + s * V_STG;
#pragma unroll
        for (int i = 0; i < 4; i++) {
            const int id = i * 256 + tid;
            const int r = id >> 4, ch = id & 15;
            const bool v = (ks + r) < S_TOK;
            const size_t gsrc = (size_t)(ks + r) * DIM + h * HD + ch * 8;
            cp_async16(Khp + r * QS + ch * 8, &g_khh[gsrc], v);
            cp_async16(Klp + r * QS + ch * 8, &g_kll[gsrc], v);
        }
#pragma unroll
        for (int i = 0; i < 4; i++) {
            const int id = i * 256 + tid;
            const int d = id >> 3, ch = id & 7;
            cp_async16(Vp + d * VS + ch * 8, &g_vt[(size_t)(h * HD + d) * VT_PAD + ks + ch * 8], true);
        }
    };

    load_kv(tiles[0], 0);
    cp_commit();

    const int row_l0 = warp * 16 + gr;
    const int row_l1 = row_l0 + 8;
    const int fi0 = (qs + row_l0) / FRAME;
    const int fi1 = (qs + row_l1) / FRAME;

    float m0 = -1e30f, m1 = -1e30f, l0 = 0.f, l1 = 0.f;
    float O[16][4];
#pragma unroll
    for (int nt = 0; nt < 16; nt++)
#pragma unroll
        for (int e = 0; e < 4; e++) O[nt][e] = 0.f;

    const float scale = 0.08838834764831845f;
    const float L2E   = 1.44269504f;
    const __half* Qh = sh + O_QH;
    const __half* Ql = sh + O_QL;
    __half* Ps = sh + O_P;

    for (int it = 0; it < ntile; it++) {
        const int s = it & 1;
        if (it + 1 < ntile) load_kv(tiles[it + 1], s ^ 1);
        cp_commit();
        cp_wait<1>();
        __syncthreads();

        const int ks0 = tiles[it];
        const __half* Kh = sh + O_K + s * K_STG;
        const __half* Vt = sh + O_V + s * V_STG;

        float Sa[8][4];
#pragma unroll
        for (int nj = 0; nj < 8; nj++)
#pragma unroll
            for (int e = 0; e < 4; e++) Sa[nj][e] = 0.f;

#pragma unroll
        for (int ks = 0; ks < 8; ks++) {
            const int kh = ks * 16 + 2 * gc;
            uint32_t ah[4], al[4];
            ah[0] = *(const uint32_t*)&Qh[row_l0 * QS + kh];
            ah[1] = *(const uint32_t*)&Qh[row_l1 * QS + kh];
            ah[2] = *(const uint32_t*)&Qh[row_l0 * QS + kh + 8];
            ah[3] = *(const uint32_t*)&Qh[row_l1 * QS + kh + 8];
            al[0] = *(const uint32_t*)&Ql[row_l0 * QS + kh];
            al[1] = *(const uint32_t*)&Ql[row_l1 * QS + kh];
            al[2] = *(const uint32_t*)&Ql[row_l0 * QS + kh + 8];
            al[3] = *(const uint32_t*)&Ql[row_l1 * QS + kh + 8];
#pragma unroll
            for (int nj = 0; nj < 8; nj++) {
                const int n = nj * 8 + gr;
                uint32_t bh0 = *(const uint32_t*)&Kh[n * QS + kh];
                uint32_t bh1 = *(const uint32_t*)&Kh[n * QS + kh + 8];
                mma_f16(Sa[nj], ah, bh0, bh1);
                mma_f16(Sa[nj], al, bh0, bh1);
            }
        }

        /* ---- scale + frame mask ---- */
        float mloc0 = -1e30f, mloc1 = -1e30f;
#pragma unroll
        for (int nj = 0; nj < 8; nj++) {
            const int cg = ks0 + nj * 8 + 2 * gc;
            const int fj = cg / FRAME;
            const bool kv = (cg < S_TOK);
            const bool ok0 = kv && (fj <= fi0) && (((fi0 - fj) < 4) || (fj == 0));
            const bool ok1 = kv && (fj <= fi1) && (((fi1 - fj) < 4) || (fj == 0));
            Sa[nj][0] = ok0 ? Sa[nj][0] * scale : -1e30f;
            Sa[nj][1] = ok0 ? Sa[nj][1] * scale : -1e30f;
            Sa[nj][2] = ok1 ? Sa[nj][2] * scale : -1e30f;
            Sa[nj][3] = ok1 ? Sa[nj][3] * scale : -1e30f;
            mloc0 = fmaxf(mloc0, fmaxf(Sa[nj][0], Sa[nj][1]));
            mloc1 = fmaxf(mloc1, fmaxf(Sa[nj][2], Sa[nj][3]));
        }
        mloc0 = fmaxf(mloc0, __shfl_xor_sync(0xffffffffu, mloc0, 1));
        mloc0 = fmaxf(mloc0, __shfl_xor_sync(0xffffffffu, mloc0, 2));
        mloc1 = fmaxf(mloc1, __shfl_xor_sync(0xffffffffu, mloc1, 1));
        mloc1 = fmaxf(mloc1, __shfl_xor_sync(0xffffffffu, mloc1, 2));

        const float mn0 = fmaxf(m0, mloc0);
        const float mn1 = fmaxf(m1, mloc1);
        const float a0 = fexp2f((m0 - mn0) * L2E);
        const float a1 = fexp2f((m1 - mn1) * L2E);
        m0 = mn0; m1 = mn1;

        /* FMA-pipe exp: p = 2^((s - mn) * log2e) */
        const float mnl0 = mn0 * L2E;
        const float mnl1 = mn1 * L2E;
        float ls0 = 0.f, ls1 = 0.f;
#pragma unroll
        for (int nj = 0; nj < 8; nj++) {
            const int cc = nj * 8 + 2 * gc;
            float p00 = fexp2f(fmaf(Sa[nj][0], L2E, -mnl0));
            float p01 = fexp2f(fmaf(Sa[nj][1], L2E, -mnl0));
            float p10 = fexp2f(fmaf(Sa[nj][2], L2E, -mnl1));
            float p11 = fexp2f(fmaf(Sa[nj][3], L2E, -mnl1));
            ls0 += p00 + p01;
            ls1 += p10 + p11;
            *(__half2*)&Ps[row_l0 * PS + cc] = __floats2half2_rn(p00, p01);
            *(__half2*)&Ps[row_l1 * PS + cc] = __floats2half2_rn(p10, p11);
        }
        ls0 += __shfl_xor_sync(0xffffffffu, ls0, 1);
        ls0 += __shfl_xor_sync(0xffffffffu, ls0, 2);
        ls1 += __shfl_xor_sync(0xffffffffu, ls1, 1);
        ls1 += __shfl_xor_sync(0xffffffffu, ls1, 2);
        l0 = l0 * a0 + ls0;
        l1 = l1 * a1 + ls1;

#pragma unroll
        for (int nt = 0; nt < 16; nt++) {
            O[nt][0] *= a0; O[nt][1] *= a0;
            O[nt][2] *= a1; O[nt][3] *= a1;
        }
        __syncwarp();

#pragma unroll
        for (int ks = 0; ks < 4; ks++) {
            const int kh = ks * 16 + 2 * gc;
            uint32_t pa[4];
            pa[0] = *(const uint32_t*)&Ps[row_l0 * PS + kh];
            pa[1] = *(const uint32_t*)&Ps[row_l1 * PS + kh];
            pa[2] = *(const uint32_t*)&Ps[row_l0 * PS + kh + 8];
            pa[3] = *(const uint32_t*)&Ps[row_l1 * PS + kh + 8];
#pragma unroll
            for (int nt = 0; nt < 16; nt++) {
                const int d = nt * 8 + gr;
                uint32_t b0 = *(const uint32_t*)&Vt[d * VS + kh];
                uint32_t b1 = *(const uint32_t*)&Vt[d * VS + kh + 8];
                mma_f16(O[nt], pa, b0, b1);
            }
        }
        __syncthreads();
    }

    const float inv0 = 1.f / l0;
    const float inv1 = 1.f / l1;
    const int rg0 = qs + row_l0;
    const int rg1 = qs + row_l1;
#pragma unroll
    for (int nt = 0; nt < 16; nt++) {
        const int col = h * HD + nt * 8 + 2 * gc;
        if (rg0 < S_TOK)
            *(__half2*)&g_oh[(size_t)rg0 * DIM + col] = __floats2half2_rn(O[nt][0] * inv0, O[nt][1] * inv0);
        if (rg1 < S_TOK)
            *(__half2*)&g_oh[(size_t)rg1 * DIM + col] = __floats2half2_rn(O[nt][2] * inv1, O[nt][3] * inv1);
    }
}

/* ================= launch ================= */
extern "C" void kernel_launch(void* const* d_in, const int* in_sizes, int n_in,
                              void* d_out, int out_size)
{
    const float* x    = (const float*)d_in[0];
    const float* fcos = (const float*)d_in[3];
    const float* fsin = (const float*)d_in[4];
    const float* Wq = (const float*)d_in[5];  const float* bq = (const float*)d_in[6];
    const float* Wk = (const float*)d_in[7];  const float* bk = (const float*)d_in[8];
    const float* Wv = (const float*)d_in[9];  const float* bv = (const float*)d_in[10];
    const float* Wo = (const float*)d_in[11]; const float* bo = (const float*)d_in[12];
    const float* gq = (const float*)d_in[13]; const float* gk = (const float*)d_in[14];
    float* out = (float*)d_out;

    __half *dwTh;
    cudaGetSymbolAddress((void**)&dwTh, g_wTh);

    transpose_half_kernel<<<dim3(48, 48, 4), 256>>>(Wq, Wk, Wv, Wo, dwTh);
    convert_x_kernel<<<(S_TOK * DIM / 4 + 255) / 256, 256>>>(x);

    gemm_qkv_kernel<<<dim3(3 * GK / BN, (S_TOK + BM - 1) / BM), 128>>>(bq, bk, bv);

    rms_rope_kernel<<<dim3(S_TOK, 2), 256>>>(fcos, fsin, gq, gk);
    v_trans_kernel<<<dim3(VT_PAD / 32, DIM / 32), 256>>>();

    cudaFuncSetAttribute(attn_f16_kernel, cudaFuncAttributeMaxDynamicSharedMemorySize, ATTN_SMEM_BYTES);
    attn_f16_kernel<<<dim3((S_TOK + TQ2 - 1) / TQ2, NH), 256, ATTN_SMEM_BYTES>>>();

    gemm_out_kernel<<<dim3(GK / BN, (S_TOK + BM - 1) / BM), 128>>>(bo, out);
}

// round 15
// speedup vs baseline: 1.0696x; 1.0696x over previous
#include <cuda_runtime.h>
#include <cuda_fp16.h>
#include <math.h>
#include <stdint.h>

#define S_TOK 3120
#define DIM   1536
#define NH    12
#define HD    128
#define FRAME 520
#define TK    64
#define GK    1536
#define VT_PAD 3136   /* 49*64 */

/* ---- scratch (static device globals) ---- */
__device__ float  g_q[S_TOK * DIM];
__device__ float  g_k[S_TOK * DIM];
__device__ float  g_v[S_TOK * DIM];
__device__ __half g_oh[S_TOK * DIM];
__device__ __half g_xh[S_TOK * DIM];
__device__ __half g_wTh[4][GK * GK];
__device__ __half g_qhh[S_TOK * DIM];
__device__ __half g_qll[S_TOK * DIM];
__device__ __half g_khh[S_TOK * DIM];
__device__ __half g_kll[S_TOK * DIM];
__device__ __half g_vt[NH * HD * VT_PAD];

__device__ __forceinline__ void mma_f16(float* c, const uint32_t* a, uint32_t b0, uint32_t b1) {
    asm volatile(
        "mma.sync.aligned.m16n8k16.row.col.f32.f16.f16.f32 "
        "{%0,%1,%2,%3}, {%4,%5,%6,%7}, {%8,%9}, {%0,%1,%2,%3};"
        : "+f"(c[0]), "+f"(c[1]), "+f"(c[2]), "+f"(c[3])
        : "r"(a[0]), "r"(a[1]), "r"(a[2]), "r"(a[3]), "r"(b0), "r"(b1));
}

__device__ __forceinline__ void ldsm_x4(uint32_t* r, uint32_t saddr) {
    asm volatile("ldmatrix.sync.aligned.m8n8.x4.shared.b16 {%0,%1,%2,%3}, [%4];"
        : "=r"(r[0]), "=r"(r[1]), "=r"(r[2]), "=r"(r[3]) : "r"(saddr));
}

__device__ __forceinline__ void cp_async16(void* smem_dst, const void* gsrc, bool valid) {
    uint32_t saddr = (uint32_t)__cvta_generic_to_shared(smem_dst);
    int sz = valid ? 16 : 0;
    asm volatile("cp.async.cg.shared.global [%0], [%1], 16, %2;\n"
                 :: "r"(saddr), "l"(gsrc), "r"(sz));
}
__device__ __forceinline__ void cp_commit() { asm volatile("cp.async.commit_group;\n"); }
template <int N>
__device__ __forceinline__ void cp_wait() { asm volatile("cp.async.wait_group %0;\n" :: "n"(N)); }

/* ============== pre-pass kernels ============== */
__global__ __launch_bounds__(256) void transpose_half_kernel(
    const float* __restrict__ w0, const float* __restrict__ w1,
    const float* __restrict__ w2, const float* __restrict__ w3,
    __half* __restrict__ dstbase)
{
    __shared__ float tile[32][33];
    const float* src = (blockIdx.z == 0) ? w0 : (blockIdx.z == 1) ? w1 : (blockIdx.z == 2) ? w2 : w3;
    __half* dst = dstbase + (size_t)blockIdx.z * GK * GK;
    const int tx = threadIdx.x & 31, ty = threadIdx.x >> 5;
    int x = blockIdx.x * 32 + tx;
    int y = blockIdx.y * 32 + ty;
#pragma unroll
    for (int i = 0; i < 32; i += 8)
        tile[ty + i][tx] = src[(size_t)(y + i) * GK + x];
    __syncthreads();
    x = blockIdx.y * 32 + tx;
    y = blockIdx.x * 32 + ty;
#pragma unroll
    for (int i = 0; i < 32; i += 8)
        dst[(size_t)(y + i) * GK + x] = __float2half_rn(tile[tx][ty + i]);
}

__global__ __launch_bounds__(256) void convert_x_kernel(const float* __restrict__ x)
{
    int i = (blockIdx.x * 256 + threadIdx.x) * 4;
    if (i < S_TOK * DIM) {
        float4 v = *(const float4*)&x[i];
        *(__half2*)&g_xh[i]     = __floats2half2_rn(v.x, v.y);
        *(__half2*)&g_xh[i + 2] = __floats2half2_rn(v.z, v.w);
    }
}

__global__ __launch_bounds__(256) void v_trans_kernel()
{
    __shared__ float tile[32][33];
    const int tx = threadIdx.x & 31, ty = threadIdx.x >> 5;
    const int t0 = blockIdx.x * 32;
    const int d0 = blockIdx.y * 32;
#pragma unroll
    for (int i = 0; i < 32; i += 8) {
        const int tok = t0 + ty + i;
        tile[ty + i][tx] = (tok < S_TOK) ? g_v[(size_t)tok * DIM + d0 + tx] : 0.f;
    }
    __syncthreads();
#pragma unroll
    for (int i = 0; i < 32; i += 8) {
        const int d = d0 + ty + i;
        g_vt[(size_t)d * VT_PAD + t0 + tx] = __float2half_rn(tile[tx][ty + i]);
    }
}

/* ============== fp16 GEMM core (128 thr, 64x64 warp tiles) ============== */
#define BM 128
#define BN 128
#define BKH 32
#define GST 40

__device__ __forceinline__ void gemm_body(
    const __half* __restrict__ A, const __half* __restrict__ Bt,
    const float* __restrict__ bias, float* __restrict__ C,
    int bm, int bn, int M)
{
    __shared__ __half As[2][BM][GST];
    __shared__ __half Bs[2][BN][GST];

    const int tid  = threadIdx.x;
    const int warp = tid >> 5;
    const int lane = tid & 31;
    const int gr   = lane >> 2;
    const int gc   = lane & 3;

    const int wm = (warp & 1) * 64;
    const int wn = (warp >> 1) * 64;

    float acc[4][8][4];
#pragma unroll
    for (int mi = 0; mi < 4; mi++)
#pragma unroll
        for (int nj = 0; nj < 8; nj++)
#pragma unroll
            for (int e = 0; e < 4; e++) acc[mi][nj][e] = 0.f;

    int crow[4]; int cc16[4];
#pragma unroll
    for (int i = 0; i < 4; i++) {
        const int cid = i * 128 + tid;
        crow[i] = cid >> 2;
        cc16[i] = cid & 3;
    }

    const int NT = GK / BKH;

#pragma unroll
    for (int i = 0; i < 4; i++) {
        cp_async16(&As[0][crow[i]][cc16[i] * 8], &A[(size_t)(bm + crow[i]) * GK + cc16[i] * 8], (bm + crow[i]) < M);
        cp_async16(&Bs[0][crow[i]][cc16[i] * 8], &Bt[(size_t)(bn + crow[i]) * GK + cc16[i] * 8], true);
    }
    cp_commit();

    for (int t = 0; t < NT; t++) {
        if (t + 1 < NT) {
            const int kt = (t + 1) * BKH;
            const int s1 = (t + 1) & 1;
#pragma unroll
            for (int i = 0; i < 4; i++) {
                cp_async16(&As[s1][crow[i]][cc16[i] * 8], &A[(size_t)(bm + crow[i]) * GK + kt + cc16[i] * 8], (bm + crow[i]) < M);
                cp_async16(&Bs[s1][crow[i]][cc16[i] * 8], &Bt[(size_t)(bn + crow[i]) * GK + kt + cc16[i] * 8], true);
            }
        }
        cp_commit();
        cp_wait<1>();
        __syncthreads();

        const int b = t & 1;
#pragma unroll
        for (int ks = 0; ks < 2; ks++) {
            const int kh = ks * 16 + 2 * gc;
            uint32_t af[4][4];
#pragma unroll
            for (int mi = 0; mi < 4; mi++) {
                const int m0 = wm + mi * 16 + gr;
                af[mi][0] = *(const uint32_t*)&As[b][m0][kh];
                af[mi][1] = *(const uint32_t*)&As[b][m0 + 8][kh];
                af[mi][2] = *(const uint32_t*)&As[b][m0][kh + 8];
                af[mi][3] = *(const uint32_t*)&As[b][m0 + 8][kh + 8];
            }
#pragma unroll
            for (int nj = 0; nj < 8; nj++) {
                const int n0 = wn + nj * 8 + gr;
                uint32_t b0 = *(const uint32_t*)&Bs[b][n0][kh];
                uint32_t b1 = *(const uint32_t*)&Bs[b][n0][kh + 8];
#pragma unroll
                for (int mi = 0; mi < 4; mi++)
                    mma_f16(acc[mi][nj], af[mi], b0, b1);
            }
        }
        __syncthreads();
    }

#pragma unroll
    for (int mi = 0; mi < 4; mi++) {
        const int row0 = bm + wm + mi * 16 + gr;
        const int row1 = row0 + 8;
#pragma unroll
        for (int nj = 0; nj < 8; nj++) {
            const int col = bn + wn + nj * 8 + 2 * gc;
            const float b0 = bias[col];
            const float b1 = bias[col + 1];
            if (row0 < M)
                *(float2*)&C[(size_t)row0 * GK + col] = make_float2(acc[mi][nj][0] + b0, acc[mi][nj][1] + b1);
            if (row1 < M)
                *(float2*)&C[(size_t)row1 * GK + col] = make_float2(acc[mi][nj][2] + b0, acc[mi][nj][3] + b1);
        }
    }
}

__global__ __launch_bounds__(128, 2) void gemm_qkv_kernel(
    const float* __restrict__ bq, const float* __restrict__ bk, const float* __restrict__ bv)
{
    const int bng = blockIdx.x * BN;
    const int which = bng / GK;
    const int bn = bng - which * GK;
    const __half* Bt = &g_wTh[which][0];
    const float* bias = (which == 0) ? bq : (which == 1) ? bk : bv;
    float* C = (which == 0) ? g_q : (which == 1) ? g_k : g_v;
    gemm_body(g_xh, Bt, bias, C, blockIdx.y * BM, bn, S_TOK);
}

__global__ __launch_bounds__(128, 2) void gemm_out_kernel(
    const float* __restrict__ bias, float* __restrict__ C)
{
    gemm_body(g_oh, &g_wTh[3][0], bias, C, blockIdx.y * BM, blockIdx.x * BN, S_TOK);
}

/* ============ fused RMSNorm + RoPE -> half hi/lo ============ */
__global__ __launch_bounds__(256) void rms_rope_kernel(
    const float* __restrict__ fcos, const float* __restrict__ fsin,
    const float* __restrict__ gq, const float* __restrict__ gk)
{
    const int row   = blockIdx.x;
    const int which = blockIdx.y;
    const float* buf = which ? g_k : g_q;
    __half* dh       = which ? g_khh : g_qhh;
    __half* dl       = which ? g_kll : g_qll;
    const float* g   = which ? gk : gq;
    const int tid    = threadIdx.x;

    const float* p = buf + (size_t)row * DIM;
    float ss = 0.f;
    for (int i = tid; i < DIM; i += 256) { float v = p[i]; ss += v * v; }

    __shared__ float red[256];
    red[tid] = ss;
    __syncthreads();
    for (int s = 128; s > 0; s >>= 1) {
        if (tid < s) red[tid] += red[tid + s];
        __syncthreads();
    }
    const float inv = rsqrtf(red[0] * (1.0f / DIM) + 1e-6f);

    const int f  = row / FRAME;
    const int hh = (row / 26) % 20;
    const int ww = row % 26;

    for (int pi = tid; pi < NH * 64; pi += 256) {
        const int head = pi >> 6;
        const int c    = pi & 63;
        const int pr   = (c < 22) ? f : ((c < 43) ? hh : ww);
        const float cs = fcos[pr * 64 + c];
        const float sn = fsin[pr * 64 + c];
        const size_t base = (size_t)row * DIM + head * HD + 2 * c;
        const float xr = buf[base]     * inv * g[head * HD + 2 * c];
        const float xi = buf[base + 1] * inv * g[head * HD + 2 * c + 1];
        const float r0 = xr * cs - xi * sn;
        const float r1 = xr * sn + xi * cs;
        const __half h0 = __float2half_rn(r0);
        const __half h1 = __float2half_rn(r1);
        *(__half2*)&dh[base] = __halves2half2(h0, h1);
        *(__half2*)&dl[base] = __floats2half2_rn(r0 - __half2float(h0), r1 - __half2float(h1));
    }
}

/* ========== fp16 flash attention: 128q x 64k, ldmatrix fragments ========== */
#define TQ2 128
#define QS 136
#define VS 72
#define PS 72
#define O_QH 0
#define O_QL (TQ2 * QS)
#define O_K  (2 * TQ2 * QS)
#define K_STG (2 * 64 * QS)
#define O_V  (O_K + 2 * K_STG)
#define V_STG (HD * VS)
#define O_P  (O_V + 2 * V_STG)
#define ATTN_HALVES (O_P + TQ2 * PS)
#define ATTN_SMEM_BYTES (ATTN_HALVES * 2)

__global__ __launch_bounds__(256) void attn_f16_kernel()
{
    extern __shared__ __half sh[];
    const int tid  = threadIdx.x;
    const int warp = tid >> 5;
    const int lane = tid & 31;
    const int gr   = lane >> 2;
    const int gc   = lane & 3;
    const int qs   = blockIdx.x * TQ2;
    const int h    = blockIdx.y;

#pragma unroll
    for (int i = 0; i < 8; i++) {
        const int id = i * 256 + tid;
        const int r = id >> 4, ch = id & 15;
        const bool v = (qs + r) < S_TOK;
        const size_t gsrc = (size_t)(qs + r) * DIM + h * HD + ch * 8;
        cp_async16(sh + O_QH + r * QS + ch * 8, &g_qhh[gsrc], v);
        cp_async16(sh + O_QL + r * QS + ch * 8, &g_qll[gsrc], v);
    }

    const int fi_min = qs / FRAME;
    const int fi_max = min(qs + TQ2 - 1, S_TOK - 1) / FRAME;
    int lo = fi_min - 3; if (lo < 0) lo = 0;
    lo *= FRAME;
    int hi = (fi_max + 1) * FRAME; if (hi > S_TOK) hi = S_TOK;
    int tiles[52]; int ntile = 0;
    if (lo <= FRAME) {
        for (int ks = 0; ks < hi; ks += TK) tiles[ntile++] = ks;
    } else {
        for (int ks = 0; ks < FRAME; ks += TK) tiles[ntile++] = ks;
        for (int ks = (lo / TK) * TK; ks < hi; ks += TK) tiles[ntile++] = ks;
    }

    auto load_kv = [&](int ks, int s) {
        __half* Khp = sh + O_K + s * K_STG;
        __half* Klp = Khp + 64 * QS;
        __half* Vp  = sh + O_V + s * V_STG;
#pragma unroll
        for (int i = 0; i < 4; i++) {
            const int id = i * 256 + tid;
            const int r = id >> 4, ch = id & 15;
            const bool v = (ks + r) < S_TOK;
            const size_t gsrc = (size_t)(ks + r) * DIM + h * HD + ch * 8;
            cp_async16(Khp + r * QS + ch * 8, &g_khh[gsrc], v);
            cp_async16(Klp + r * QS + ch * 8, &g_kll[gsrc], v);
        }
#pragma unroll
        for (int i = 0; i < 4; i++) {
            const int id = i * 256 + tid;
            const int d = id >> 3, ch = id & 7;
            cp_async16(Vp + d * VS + ch * 8, &g_vt[(size_t)(h * HD + d) * VT_PAD + ks + ch * 8], true);
        }
    };

    load_kv(tiles[0], 0);
    cp_commit();

    const int row_l0 = warp * 16 + gr;
    const int row_l1 = row_l0 + 8;
    const int fi0 = (qs + row_l0) / FRAME;
    const int fi1 = (qs + row_l1) / FRAME;

    /* ldmatrix per-lane base offsets (halves) */
    const int sub = lane & 7, seg = lane >> 3;
    const int a_row = (seg & 1) * 8 + sub;         /* A-type: regs {(r,c),(r+8,c),(r,c+8),(r+8,c+8)} */
    const int a_col = (seg >> 1) * 8;
    const int b_row = ((seg >> 1) & 1) * 8 + sub;  /* B-type: regs {(n,c),(n,c+8),(n+8,c),(n+8,c+8)} */
    const int b_col = (seg & 1) * 8;

    const uint32_t shb  = (uint32_t)__cvta_generic_to_shared(sh);
    const uint32_t qh_b = shb + 2 * (O_QH + (warp * 16 + a_row) * QS + a_col);
    const uint32_t ql_b = shb + 2 * (O_QL + (warp * 16 + a_row) * QS + a_col);
    const uint32_t ps_b = shb + 2 * (O_P  + (warp * 16 + a_row) * PS + a_col);

    float m0 = -1e30f, m1 = -1e30f, l0 = 0.f, l1 = 0.f;
    float O[16][4];
#pragma unroll
    for (int nt = 0; nt < 16; nt++)
#pragma unroll
        for (int e = 0; e < 4; e++) O[nt][e] = 0.f;

    const float scale = 0.08838834764831845f;
    __half* Ps = sh + O_P;

    for (int it = 0; it < ntile; it++) {
        const int s = it & 1;
        if (it + 1 < ntile) load_kv(tiles[it + 1], s ^ 1);
        cp_commit();
        cp_wait<1>();
        __syncthreads();

        const int ks0 = tiles[it];
        const uint32_t kh_b = shb + 2 * (O_K + s * K_STG + b_row * QS + b_col);
        const uint32_t vt_b = shb + 2 * (O_V + s * V_STG + b_row * VS + b_col);

        /* ---- QK^T (2-term compensated fp16, ldmatrix fragments) ---- */
        float Sa[8][4];
#pragma unroll
        for (int nj = 0; nj < 8; nj++)
#pragma unroll
            for (int e = 0; e < 4; e++) Sa[nj][e] = 0.f;

#pragma unroll
        for (int ks = 0; ks < 8; ks++) {
            uint32_t ah[4], al[4];
            ldsm_x4(ah, qh_b + 2 * (ks * 16));
            ldsm_x4(al, ql_b + 2 * (ks * 16));
#pragma unroll
            for (int njp = 0; njp < 4; njp++) {
                uint32_t bb[4];
                ldsm_x4(bb, kh_b + 2 * (njp * 16 * QS + ks * 16));
                mma_f16(Sa[2 * njp],     ah, bb[0], bb[1]);
                mma_f16(Sa[2 * njp],     al, bb[0], bb[1]);
                mma_f16(Sa[2 * njp + 1], ah, bb[2], bb[3]);
                mma_f16(Sa[2 * njp + 1], al, bb[2], bb[3]);
            }
        }

        /* ---- scale + frame mask ---- */
        float mloc0 = -1e30f, mloc1 = -1e30f;
#pragma unroll
        for (int nj = 0; nj < 8; nj++) {
            const int cg = ks0 + nj * 8 + 2 * gc;
            const int fj = cg / FRAME;
            const bool kv = (cg < S_TOK);
            const bool ok0 = kv && (fj <= fi0) && (((fi0 - fj) < 4) || (fj == 0));
            const bool ok1 = kv && (fj <= fi1) && (((fi1 - fj) < 4) || (fj == 0));
            Sa[nj][0] = ok0 ? Sa[nj][0] * scale : -1e30f;
            Sa[nj][1] = ok0 ? Sa[nj][1] * scale : -1e30f;
            Sa[nj][2] = ok1 ? Sa[nj][2] * scale : -1e30f;
            Sa[nj][3] = ok1 ? Sa[nj][3] * scale : -1e30f;
            mloc0 = fmaxf(mloc0, fmaxf(Sa[nj][0], Sa[nj][1]));
            mloc1 = fmaxf(mloc1, fmaxf(Sa[nj][2], Sa[nj][3]));
        }
        mloc0 = fmaxf(mloc0, __shfl_xor_sync(0xffffffffu, mloc0, 1));
        mloc0 = fmaxf(mloc0, __shfl_xor_sync(0xffffffffu, mloc0, 2));
        mloc1 = fmaxf(mloc1, __shfl_xor_sync(0xffffffffu, mloc1, 1));
        mloc1 = fmaxf(mloc1, __shfl_xor_sync(0xffffffffu, mloc1, 2));

        const float mn0 = fmaxf(m0, mloc0);
        const float mn1 = fmaxf(m1, mloc1);
        const float a0 = __expf(m0 - mn0);
        const float a1 = __expf(m1 - mn1);
        m0 = mn0; m1 = mn1;

        float ls0 = 0.f, ls1 = 0.f;
#pragma unroll
        for (int nj = 0; nj < 8; nj++) {
            const int cc = nj * 8 + 2 * gc;
            float p00 = __expf(Sa[nj][0] - mn0);
            float p01 = __expf(Sa[nj][1] - mn0);
            float p10 = __expf(Sa[nj][2] - mn1);
            float p11 = __expf(Sa[nj][3] - mn1);
            ls0 += p00 + p01;
            ls1 += p10 + p11;
            *(__half2*)&Ps[row_l0 * PS + cc] = __floats2half2_rn(p00, p01);
            *(__half2*)&Ps[row_l1 * PS + cc] = __floats2half2_rn(p10, p11);
        }
        ls0 += __shfl_xor_sync(0xffffffffu, ls0, 1);
        ls0 += __shfl_xor_sync(0xffffffffu, ls0, 2);
        ls1 += __shfl_xor_sync(0xffffffffu, ls1, 1);
        ls1 += __shfl_xor_sync(0xffffffffu, ls1, 2);
        l0 = l0 * a0 + ls0;
        l1 = l1 * a1 + ls1;

#pragma unroll
        for (int nt = 0; nt < 16; nt++) {
            O[nt][0] *= a0; O[nt][1] *= a0;
            O[nt][2] *= a1; O[nt][3] *= a1;
        }
        __syncwarp();

        /* ---- P @ V (ldmatrix fragments) ---- */
#pragma unroll
        for (int ks = 0; ks < 4; ks++) {
            uint32_t pa[4];
            ldsm_x4(pa, ps_b + 2 * (ks * 16));
#pragma unroll
            for (int ntp = 0; ntp < 8; ntp++) {
                uint32_t bb[4];
                ldsm_x4(bb, vt_b + 2 * (ntp * 16 * VS + ks * 16));
                mma_f16(O[2 * ntp],     pa, bb[0], bb[1]);
                mma_f16(O[2 * ntp + 1], pa, bb[2], bb[3]);
            }
        }
        __syncthreads();
    }

    const float inv0 = 1.f / l0;
    const float inv1 = 1.f / l1;
    const int rg0 = qs + row_l0;
    const int rg1 = qs + row_l1;
#pragma unroll
    for (int nt = 0; nt < 16; nt++) {
        const int col = h * HD + nt * 8 + 2 * gc;
        if (rg0 < S_TOK)
            *(__half2*)&g_oh[(size_t)rg0 * DIM + col] = __floats2half2_rn(O[nt][0] * inv0, O[nt][1] * inv0);
        if (rg1 < S_TOK)
            *(__half2*)&g_oh[(size_t)rg1 * DIM + col] = __floats2half2_rn(O[nt][2] * inv1, O[nt][3] * inv1);
    }
}

/* ================= launch ================= */
extern "C" void kernel_launch(void* const* d_in, const int* in_sizes, int n_in,
                              void* d_out, int out_size)
{
    const float* x    = (const float*)d_in[0];
    const float* fcos = (const float*)d_in[3];
    const float* fsin = (const float*)d_in[4];
    const float* Wq = (const float*)d_in[5];  const float* bq = (const float*)d_in[6];
    const float* Wk = (const float*)d_in[7];  const float* bk = (const float*)d_in[8];
    const float* Wv = (const float*)d_in[9];  const float* bv = (const float*)d_in[10];
    const float* Wo = (const float*)d_in[11]; const float* bo = (const float*)d_in[12];
    const float* gq = (const float*)d_in[13]; const float* gk = (const float*)d_in[14];
    float* out = (float*)d_out;

    __half *dwTh;
    cudaGetSymbolAddress((void**)&dwTh, g_wTh);

    transpose_half_kernel<<<dim3(48, 48, 4), 256>>>(Wq, Wk, Wv, Wo, dwTh);
    convert_x_kernel<<<(S_TOK * DIM / 4 + 255) / 256, 256>>>(x);

    gemm_qkv_kernel<<<dim3(3 * GK / BN, (S_TOK + BM - 1) / BM), 128>>>(bq, bk, bv);

    rms_rope_kernel<<<dim3(S_TOK, 2), 256>>>(fcos, fsin, gq, gk);
    v_trans_kernel<<<dim3(VT_PAD / 32, DIM / 32), 256>>>();

    cudaFuncSetAttribute(attn_f16_kernel, cudaFuncAttributeMaxDynamicSharedMemorySize, ATTN_SMEM_BYTES);
    attn_f16_kernel<<<dim3((S_TOK + TQ2 - 1) / TQ2, NH), 256, ATTN_SMEM_BYTES>>>();

    gemm_out_kernel<<<dim3(GK / BN, (S_TOK + BM - 1) / BM), 128>>>(bo, out);
}

// round 17
// speedup vs baseline: 1.1747x; 1.0983x over previous
#include <cuda_runtime.h>
#include <cuda_fp16.h>
#include <math.h>
#include <stdint.h>

#define S_TOK 3120
#define DIM   1536
#define NH    12
#define HD    128
#define FRAME 520
#define TK    64
#define GK    1536
#define VT_PAD 3136   /* 49*64 */

/* ---- scratch (static device globals) ---- */
__device__ float  g_q[S_TOK * DIM];
__device__ float  g_k[S_TOK * DIM];
__device__ float  g_v[S_TOK * DIM];
__device__ __half g_oh[S_TOK * DIM];
__device__ __half g_xh[S_TOK * DIM];
__device__ __half g_wTh[4][GK * GK];
__device__ __half g_qhh[S_TOK * DIM];
__device__ __half g_qll[S_TOK * DIM];
__device__ __half g_khh[S_TOK * DIM];
__device__ __half g_vt[NH * HD * VT_PAD];

__device__ __forceinline__ void mma_f16(float* c, const uint32_t* a, uint32_t b0, uint32_t b1) {
    asm volatile(
        "mma.sync.aligned.m16n8k16.row.col.f32.f16.f16.f32 "
        "{%0,%1,%2,%3}, {%4,%5,%6,%7}, {%8,%9}, {%0,%1,%2,%3};"
        : "+f"(c[0]), "+f"(c[1]), "+f"(c[2]), "+f"(c[3])
        : "r"(a[0]), "r"(a[1]), "r"(a[2]), "r"(a[3]), "r"(b0), "r"(b1));
}

__device__ __forceinline__ void ldsm_x4(uint32_t* r, uint32_t saddr) {
    asm volatile("ldmatrix.sync.aligned.m8n8.x4.shared.b16 {%0,%1,%2,%3}, [%4];"
        : "=r"(r[0]), "=r"(r[1]), "=r"(r[2]), "=r"(r[3]) : "r"(saddr));
}

__device__ __forceinline__ void cp_async16(void* smem_dst, const void* gsrc, bool valid) {
    uint32_t saddr = (uint32_t)__cvta_generic_to_shared(smem_dst);
    int sz = valid ? 16 : 0;
    asm volatile("cp.async.cg.shared.global [%0], [%1], 16, %2;\n"
                 :: "r"(saddr), "l"(gsrc), "r"(sz));
}
__device__ __forceinline__ void cp_commit() { asm volatile("cp.async.commit_group;\n"); }
template <int N>
__device__ __forceinline__ void cp_wait() { asm volatile("cp.async.wait_group %0;\n" :: "n"(N)); }

/* ============== pre-pass kernels ============== */
__global__ __launch_bounds__(256) void transpose_half_kernel(
    const float* __restrict__ w0, const float* __restrict__ w1,
    const float* __restrict__ w2, const float* __restrict__ w3,
    __half* __restrict__ dstbase)
{
    __shared__ float tile[32][33];
    const float* src = (blockIdx.z == 0) ? w0 : (blockIdx.z == 1) ? w1 : (blockIdx.z == 2) ? w2 : w3;
    __half* dst = dstbase + (size_t)blockIdx.z * GK * GK;
    const int tx = threadIdx.x & 31, ty = threadIdx.x >> 5;
    int x = blockIdx.x * 32 + tx;
    int y = blockIdx.y * 32 + ty;
#pragma unroll
    for (int i = 0; i < 32; i += 8)
        tile[ty + i][tx] = src[(size_t)(y + i) * GK + x];
    __syncthreads();
    x = blockIdx.y * 32 + tx;
    y = blockIdx.x * 32 + ty;
#pragma unroll
    for (int i = 0; i < 32; i += 8)
        dst[(size_t)(y + i) * GK + x] = __float2half_rn(tile[tx][ty + i]);
}

__global__ __launch_bounds__(256) void convert_x_kernel(const float* __restrict__ x)
{
    int i = (blockIdx.x * 256 + threadIdx.x) * 4;
    if (i < S_TOK * DIM) {
        float4 v = *(const float4*)&x[i];
        *(__half2*)&g_xh[i]     = __floats2half2_rn(v.x, v.y);
        *(__half2*)&g_xh[i + 2] = __floats2half2_rn(v.z, v.w);
    }
}

__global__ __launch_bounds__(256) void v_trans_kernel()
{
    __shared__ float tile[32][33];
    const int tx = threadIdx.x & 31, ty = threadIdx.x >> 5;
    const int t0 = blockIdx.x * 32;
    const int d0 = blockIdx.y * 32;
#pragma unroll
    for (int i = 0; i < 32; i += 8) {
        const int tok = t0 + ty + i;
        tile[ty + i][tx] = (tok < S_TOK) ? g_v[(size_t)tok * DIM + d0 + tx] : 0.f;
    }
    __syncthreads();
#pragma unroll
    for (int i = 0; i < 32; i += 8) {
        const int d = d0 + ty + i;
        g_vt[(size_t)d * VT_PAD + t0 + tx] = __float2half_rn(tile[tx][ty + i]);
    }
}

/* ============== fp16 GEMM core (128 thr, 64x64 warp tiles, ldmatrix) ============== */
#define BM 128
#define BN 128
#define BKH 32
#define GST 40

__device__ __forceinline__ void gemm_body(
    const __half* __restrict__ A, const __half* __restrict__ Bt,
    const float* __restrict__ bias, float* __restrict__ C,
    int bm, int bn, int M)
{
    __shared__ __half As[2][BM][GST];
    __shared__ __half Bs[2][BN][GST];

    const int tid  = threadIdx.x;
    const int warp = tid >> 5;
    const int lane = tid & 31;
    const int gr   = lane >> 2;
    const int gc   = lane & 3;

    const int wm = (warp & 1) * 64;
    const int wn = (warp >> 1) * 64;

    float acc[4][8][4];
#pragma unroll
    for (int mi = 0; mi < 4; mi++)
#pragma unroll
        for (int nj = 0; nj < 8; nj++)
#pragma unroll
            for (int e = 0; e < 4; e++) acc[mi][nj][e] = 0.f;

    int crow[4]; int cc16[4];
#pragma unroll
    for (int i = 0; i < 4; i++) {
        const int cid = i * 128 + tid;
        crow[i] = cid >> 2;
        cc16[i] = cid & 3;
    }

    /* ldmatrix lane bases */
    const int sub = lane & 7, seg = lane >> 3;
    const int a_row = (seg & 1) * 8 + sub;
    const int a_col = (seg >> 1) * 8;
    const int b_row = ((seg >> 1) & 1) * 8 + sub;
    const int b_col = (seg & 1) * 8;
    uint32_t as_base[2], bs_base[2];
#pragma unroll
    for (int b = 0; b < 2; b++) {
        as_base[b] = (uint32_t)__cvta_generic_to_shared(&As[b][wm + a_row][a_col]);
        bs_base[b] = (uint32_t)__cvta_generic_to_shared(&Bs[b][wn + b_row][b_col]);
    }

    const int NT = GK / BKH;

#pragma unroll
    for (int i = 0; i < 4; i++) {
        cp_async16(&As[0][crow[i]][cc16[i] * 8], &A[(size_t)(bm + crow[i]) * GK + cc16[i] * 8], (bm + crow[i]) < M);
        cp_async16(&Bs[0][crow[i]][cc16[i] * 8], &Bt[(size_t)(bn + crow[i]) * GK + cc16[i] * 8], true);
    }
    cp_commit();

    for (int t = 0; t < NT; t++) {
        if (t + 1 < NT) {
            const int kt = (t + 1) * BKH;
            const int s1 = (t + 1) & 1;
#pragma unroll
            for (int i = 0; i < 4; i++) {
                cp_async16(&As[s1][crow[i]][cc16[i] * 8], &A[(size_t)(bm + crow[i]) * GK + kt + cc16[i] * 8], (bm + crow[i]) < M);
                cp_async16(&Bs[s1][crow[i]][cc16[i] * 8], &Bt[(size_t)(bn + crow[i]) * GK + kt + cc16[i] * 8], true);
            }
        }
        cp_commit();
        cp_wait<1>();
        __syncthreads();

        const int b = t & 1;
#pragma unroll
        for (int ks = 0; ks < 2; ks++) {
            uint32_t af[4][4];
#pragma unroll
            for (int mi = 0; mi < 4; mi++)
                ldsm_x4(af[mi], as_base[b] + 2 * (mi * 16 * GST + ks * 16));
#pragma unroll
            for (int njp = 0; njp < 4; njp++) {
                uint32_t bb[4];
                ldsm_x4(bb, bs_base[b] + 2 * (njp * 16 * GST + ks * 16));
#pragma unroll
                for (int mi = 0; mi < 4; mi++) {
                    mma_f16(acc[mi][2 * njp],     af[mi], bb[0], bb[1]);
                    mma_f16(acc[mi][2 * njp + 1], af[mi], bb[2], bb[3]);
                }
            }
        }
        __syncthreads();
    }

#pragma unroll
    for (int mi = 0; mi < 4; mi++) {
        const int row0 = bm + wm + mi * 16 + gr;
        const int row1 = row0 + 8;
#pragma unroll
        for (int nj = 0; nj < 8; nj++) {
            const int col = bn + wn + nj * 8 + 2 * gc;
            const float b0 = bias[col];
            const float b1 = bias[col + 1];
            if (row0 < M)
                *(float2*)&C[(size_t)row0 * GK + col] = make_float2(acc[mi][nj][0] + b0, acc[mi][nj][1] + b1);
            if (row1 < M)
                *(float2*)&C[(size_t)row1 * GK + col] = make_float2(acc[mi][nj][2] + b0, acc[mi][nj][3] + b1);
        }
    }
}

__global__ __launch_bounds__(128, 2) void gemm_qkv_kernel(
    const float* __restrict__ bq, const float* __restrict__ bk, const float* __restrict__ bv)
{
    const int bng = blockIdx.x * BN;
    const int which = bng / GK;
    const int bn = bng - which * GK;
    const __half* Bt = &g_wTh[which][0];
    const float* bias = (which == 0) ? bq : (which == 1) ? bk : bv;
    float* C = (which == 0) ? g_q : (which == 1) ? g_k : g_v;
    gemm_body(g_xh, Bt, bias, C, blockIdx.y * BM, bn, S_TOK);
}

__global__ __launch_bounds__(128, 2) void gemm_out_kernel(
    const float* __restrict__ bias, float* __restrict__ C)
{
    gemm_body(g_oh, &g_wTh[3][0], bias, C, blockIdx.y * BM, blockIdx.x * BN, S_TOK);
}

/* ============ fused RMSNorm + RoPE -> half (hi/lo for Q, hi only for K) ============ */
__global__ __launch_bounds__(256) void rms_rope_kernel(
    const float* __restrict__ fcos, const float* __restrict__ fsin,
    const float* __restrict__ gq, const float* __restrict__ gk)
{
    const int row   = blockIdx.x;
    const int which = blockIdx.y;
    const float* buf = which ? g_k : g_q;
    __half* dh       = which ? g_khh : g_qhh;
    const float* g   = which ? gk : gq;
    const int tid    = threadIdx.x;

    const float* p = buf + (size_t)row * DIM;
    float ss = 0.f;
    for (int i = tid; i < DIM; i += 256) { float v = p[i]; ss += v * v; }

    __shared__ float red[256];
    red[tid] = ss;
    __syncthreads();
    for (int s = 128; s > 0; s >>= 1) {
        if (tid < s) red[tid] += red[tid + s];
        __syncthreads();
    }
    const float inv = rsqrtf(red[0] * (1.0f / DIM) + 1e-6f);

    const int f  = row / FRAME;
    const int hh = (row / 26) % 20;
    const int ww = row % 26;

    for (int pi = tid; pi < NH * 64; pi += 256) {
        const int head = pi >> 6;
        const int c    = pi & 63;
        const int pr   = (c < 22) ? f : ((c < 43) ? hh : ww);
        const float cs = fcos[pr * 64 + c];
        const float sn = fsin[pr * 64 + c];
        const size_t base = (size_t)row * DIM + head * HD + 2 * c;
        const float xr = buf[base]     * inv * g[head * HD + 2 * c];
        const float xi = buf[base + 1] * inv * g[head * HD + 2 * c + 1];
        const float r0 = xr * cs - xi * sn;
        const float r1 = xr * sn + xi * cs;
        const __half h0 = __float2half_rn(r0);
        const __half h1 = __float2half_rn(r1);
        *(__half2*)&dh[base] = __halves2half2(h0, h1);
        if (which == 0)
            *(__half2*)&g_qll[base] = __floats2half2_rn(r0 - __half2float(h0), r1 - __half2float(h1));
    }
}

/* ========== fp16 flash attention: 128q x 64k, ldmatrix, no dead Kl ========== */
#define TQ2 128
#define QS 136
#define VS 72
#define PS 72
#define O_QH 0
#define O_QL (TQ2 * QS)
#define O_K  (2 * TQ2 * QS)
#define K_STG (64 * QS)               /* hi only */
#define O_V  (O_K + 2 * K_STG)
#define V_STG (HD * VS)
#define O_P  (O_V + 2 * V_STG)
#define ATTN_HALVES (O_P + TQ2 * PS)
#define ATTN_SMEM_BYTES (ATTN_HALVES * 2)   /* ~160 KB */

__global__ __launch_bounds__(256) void attn_f16_kernel()
{
    extern __shared__ __half sh[];
    const int tid  = threadIdx.x;
    const int warp = tid >> 5;
    const int lane = tid & 31;
    const int gr   = lane >> 2;
    const int gc   = lane & 3;
    const int qs   = blockIdx.x * TQ2;
    const int h    = blockIdx.y;

#pragma unroll
    for (int i = 0; i < 8; i++) {
        const int id = i * 256 + tid;
        const int r = id >> 4, ch = id & 15;
        const bool v = (qs + r) < S_TOK;
        const size_t gsrc = (size_t)(qs + r) * DIM + h * HD + ch * 8;
        cp_async16(sh + O_QH + r * QS + ch * 8, &g_qhh[gsrc], v);
        cp_async16(sh + O_QL + r * QS + ch * 8, &g_qll[gsrc], v);
    }

    const int fi_min = qs / FRAME;
    const int fi_max = min(qs + TQ2 - 1, S_TOK - 1) / FRAME;
    int lo = fi_min - 3; if (lo < 0) lo = 0;
    lo *= FRAME;
    int hi = (fi_max + 1) * FRAME; if (hi > S_TOK) hi = S_TOK;
    int tiles[52]; int ntile = 0;
    if (lo <= FRAME) {
        for (int ks = 0; ks < hi; ks += TK) tiles[ntile++] = ks;
    } else {
        for (int ks = 0; ks < FRAME; ks += TK) tiles[ntile++] = ks;
        for (int ks = (lo / TK) * TK; ks < hi; ks += TK) tiles[ntile++] = ks;
    }

    auto load_kv = [&](int ks, int s) {
        __half* Khp = sh + O_K + s * K_STG;
        __half* Vp  = sh + O_V + s * V_STG;
#pragma unroll
        for (int i = 0; i < 4; i++) {
            const int id = i * 256 + tid;
            const int r = id >> 4, ch = id & 15;
            const bool v = (ks + r) < S_TOK;
            cp_async16(Khp + r * QS + ch * 8, &g_khh[(size_t)(ks + r) * DIM + h * HD + ch * 8], v);
        }
#pragma unroll
        for (int i = 0; i < 4; i++) {
            const int id = i * 256 + tid;
            const int d = id >> 3, ch = id & 7;
            cp_async16(Vp + d * VS + ch * 8, &g_vt[(size_t)(h * HD + d) * VT_PAD + ks + ch * 8], true);
        }
    };

    load_kv(tiles[0], 0);
    cp_commit();

    const int row_l0 = warp * 16 + gr;
    const int row_l1 = row_l0 + 8;
    const int fi0 = (qs + row_l0) / FRAME;
    const int fi1 = (qs + row_l1) / FRAME;

    /* ldmatrix per-lane base offsets (halves) */
    const int sub = lane & 7, seg = lane >> 3;
    const int a_row = (seg & 1) * 8 + sub;
    const int a_col = (seg >> 1) * 8;
    const int b_row = ((seg >> 1) & 1) * 8 + sub;
    const int b_col = (seg & 1) * 8;

    const uint32_t shb  = (uint32_t)__cvta_generic_to_shared(sh);
    const uint32_t qh_b = shb + 2 * (O_QH + (warp * 16 + a_row) * QS + a_col);
    const uint32_t ql_b = shb + 2 * (O_QL + (warp * 16 + a_row) * QS + a_col);
    const uint32_t ps_b = shb + 2 * (O_P  + (warp * 16 + a_row) * PS + a_col);

    float m0 = -1e30f, m1 = -1e30f, l0 = 0.f, l1 = 0.f;
    float O[16][4];
#pragma unroll
    for (int nt = 0; nt < 16; nt++)
#pragma unroll
        for (int e = 0; e < 4; e++) O[nt][e] = 0.f;

    const float scale = 0.08838834764831845f;
    __half* Ps = sh + O_P;

    for (int it = 0; it < ntile; it++) {
        const int s = it & 1;
        if (it + 1 < ntile) load_kv(tiles[it + 1], s ^ 1);
        cp_commit();
        cp_wait<1>();
        __syncthreads();

        const int ks0 = tiles[it];
        const uint32_t kh_b = shb + 2 * (O_K + s * K_STG + b_row * QS + b_col);
        const uint32_t vt_b = shb + 2 * (O_V + s * V_STG + b_row * VS + b_col);

        /* ---- QK^T (2-term compensated fp16, ldmatrix fragments) ---- */
        float Sa[8][4];
#pragma unroll
        for (int nj = 0; nj < 8; nj++)
#pragma unroll
            for (int e = 0; e < 4; e++) Sa[nj][e] = 0.f;

#pragma unroll
        for (int ks = 0; ks < 8; ks++) {
            uint32_t ah[4], al[4];
            ldsm_x4(ah, qh_b + 2 * (ks * 16));
            ldsm_x4(al, ql_b + 2 * (ks * 16));
#pragma unroll
            for (int njp = 0; njp < 4; njp++) {
                uint32_t bb[4];
                ldsm_x4(bb, kh_b + 2 * (njp * 16 * QS + ks * 16));
                mma_f16(Sa[2 * njp],     ah, bb[0], bb[1]);
                mma_f16(Sa[2 * njp],     al, bb[0], bb[1]);
                mma_f16(Sa[2 * njp + 1], ah, bb[2], bb[3]);
                mma_f16(Sa[2 * njp + 1], al, bb[2], bb[3]);
            }
        }

        /* ---- scale + frame mask ---- */
        float mloc0 = -1e30f, mloc1 = -1e30f;
#pragma unroll
        for (int nj = 0; nj < 8; nj++) {
            const int cg = ks0 + nj * 8 + 2 * gc;
            const int fj = cg / FRAME;
            const bool kv = (cg < S_TOK);
            const bool ok0 = kv && (fj <= fi0) && (((fi0 - fj) < 4) || (fj == 0));
            const bool ok1 = kv && (fj <= fi1) && (((fi1 - fj) < 4) || (fj == 0));
            Sa[nj][0] = ok0 ? Sa[nj][0] * scale : -1e30f;
            Sa[nj][1] = ok0 ? Sa[nj][1] * scale : -1e30f;
            Sa[nj][2] = ok1 ? Sa[nj][2] * scale : -1e30f;
            Sa[nj][3] = ok1 ? Sa[nj][3] * scale : -1e30f;
            mloc0 = fmaxf(mloc0, fmaxf(Sa[nj][0], Sa[nj][1]));
            mloc1 = fmaxf(mloc1, fmaxf(Sa[nj][2], Sa[nj][3]));
        }
        mloc0 = fmaxf(mloc0, __shfl_xor_sync(0xffffffffu, mloc0, 1));
        mloc0 = fmaxf(mloc0, __shfl_xor_sync(0xffffffffu, mloc0, 2));
        mloc1 = fmaxf(mloc1, __shfl_xor_sync(0xffffffffu, mloc1, 1));
        mloc1 = fmaxf(mloc1, __shfl_xor_sync(0xffffffffu, mloc1, 2));

        const float mn0 = fmaxf(m0, mloc0);
        const float mn1 = fmaxf(m1, mloc1);
        const float a0 = __expf(m0 - mn0);
        const float a1 = __expf(m1 - mn1);
        m0 = mn0; m1 = mn1;

        float ls0 = 0.f, ls1 = 0.f;
#pragma unroll
        for (int nj = 0; nj < 8; nj++) {
            const int cc = nj * 8 + 2 * gc;
            float p00 = __expf(Sa[nj][0] - mn0);
            float p01 = __expf(Sa[nj][1] - mn0);
            float p10 = __expf(Sa[nj][2] - mn1);
            float p11 = __expf(Sa[nj][3] - mn1);
            ls0 += p00 + p01;
            ls1 += p10 + p11;
            *(__half2*)&Ps[row_l0 * PS + cc] = __floats2half2_rn(p00, p01);
            *(__half2*)&Ps[row_l1 * PS + cc] = __floats2half2_rn(p10, p11);
        }
        ls0 += __shfl_xor_sync(0xffffffffu, ls0, 1);
        ls0 += __shfl_xor_sync(0xffffffffu, ls0, 2);
        ls1 += __shfl_xor_sync(0xffffffffu, ls1, 1);
        ls1 += __shfl_xor_sync(0xffffffffu, ls1, 2);
        l0 = l0 * a0 + ls0;
        l1 = l1 * a1 + ls1;

#pragma unroll
        for (int nt = 0; nt < 16; nt++) {
            O[nt][0] *= a0; O[nt][1] *= a0;
            O[nt][2] *= a1; O[nt][3] *= a1;
        }
        __syncwarp();

        /* ---- P @ V (ldmatrix fragments) ---- */
#pragma unroll
        for (int ks = 0; ks < 4; ks++) {
            uint32_t pa[4];
            ldsm_x4(pa, ps_b + 2 * (ks * 16));
#pragma unroll
            for (int ntp = 0; ntp < 8; ntp++) {
                uint32_t bb[4];
                ldsm_x4(bb, vt_b + 2 * (ntp * 16 * VS + ks * 16));
                mma_f16(O[2 * ntp],     pa, bb[0], bb[1]);
                mma_f16(O[2 * ntp + 1], pa, bb[2], bb[3]);
            }
        }
        __syncthreads();
    }

    const float inv0 = 1.f / l0;
    const float inv1 = 1.f / l1;
    const int rg0 = qs + row_l0;
    const int rg1 = qs + row_l1;
#pragma unroll
    for (int nt = 0; nt < 16; nt++) {
        const int col = h * HD + nt * 8 + 2 * gc;
        if (rg0 < S_TOK)
            *(__half2*)&g_oh[(size_t)rg0 * DIM + col] = __floats2half2_rn(O[nt][0] * inv0, O[nt][1] * inv0);
        if (rg1 < S_TOK)
            *(__half2*)&g_oh[(size_t)rg1 * DIM + col] = __floats2half2_rn(O[nt][2] * inv1, O[nt][3] * inv1);
    }
}

/* ================= launch ================= */
extern "C" void kernel_launch(void* const* d_in, const int* in_sizes, int n_in,
                              void* d_out, int out_size)
{
    const float* x    = (const float*)d_in[0];
    const float* fcos = (const float*)d_in[3];
    const float* fsin = (const float*)d_in[4];
    const float* Wq = (const float*)d_in[5];  const float* bq = (const float*)d_in[6];
    const float* Wk = (const float*)d_in[7];  const float* bk = (const float*)d_in[8];
    const float* Wv = (const float*)d_in[9];  const float* bv = (const float*)d_in[10];
    const float* Wo = (const float*)d_in[11]; const float* bo = (const float*)d_in[12];
    const float* gq = (const float*)d_in[13]; const float* gk = (const float*)d_in[14];
    float* out = (float*)d_out;

    __half *dwTh;
    cudaGetSymbolAddress((void**)&dwTh, g_wTh);

    transpose_half_kernel<<<dim3(48, 48, 4), 256>>>(Wq, Wk, Wv, Wo, dwTh);
    convert_x_kernel<<<(S_TOK * DIM / 4 + 255) / 256, 256>>>(x);

    gemm_qkv_kernel<<<dim3(3 * GK / BN, (S_TOK + BM - 1) / BM), 128>>>(bq, bk, bv);

    rms_rope_kernel<<<dim3(S_TOK, 2), 256>>>(fcos, fsin, gq, gk);
    v_trans_kernel<<<dim3(VT_PAD / 32, DIM / 32), 256>>>();

    cudaFuncSetAttribute(attn_f16_kernel, cudaFuncAttributeMaxDynamicSharedMemorySize, ATTN_SMEM_BYTES);
    attn_f16_kernel<<<dim3((S_TOK + TQ2 - 1) / TQ2, NH), 256, ATTN_SMEM_BYTES>>>();

    gemm_out_kernel<<<dim3(GK / BN, (S_TOK + BM - 1) / BM), 128>>>(bo, out);
}